// round 2
// baseline (speedup 1.0000x reference)
#include <cuda_runtime.h>
#include <math.h>
#include <stddef.h>

#define BATCH 8
#define NT 1024
#define TD 128
#define HID 512
#define NH 8
#define HD 64

typedef unsigned long long u64;

// packed f32x2 helpers (sm_100+ PTX; ptxas never auto-fuses these)
__device__ __forceinline__ void ffma2(u64 &d, u64 a, u64 b) {
    asm("fma.rn.f32x2 %0, %1, %2, %0;" : "+l"(d) : "l"(a), "l"(b));
}
__device__ __forceinline__ void fmul2(u64 &d, u64 a, u64 b) {
    asm("mul.rn.f32x2 %0, %1, %2;" : "=l"(d) : "l"(a), "l"(b));
}
__device__ __forceinline__ u64 pack2(float lo, float hi) {
    u64 r; asm("mov.b64 %0, {%1, %2};" : "=l"(r) : "f"(lo), "f"(hi)); return r;
}
__device__ __forceinline__ void unpack2(u64 v, float &lo, float &hi) {
    asm("mov.b64 {%0, %1}, %2;" : "=f"(lo), "=f"(hi) : "l"(v));
}

// ---------------- device scratch (static; no allocation) ----------------
__device__ unsigned g_tmax_u;
__device__ float g_twm[BATCH * NT * NT];     // adj ? exp(-0.1*(tmax-t)) : -1
__device__ float g_struct[NT * HID];
__device__ float g_bt[HID * HID];            // transposed weight staging
__device__ float g_h[BATCH * NT * HID];      // h per (b,n,[h*64+d])
__device__ float g_node[BATCH * NT * HID];   // GAT layer output
__device__ float g_esrc[BATCH * NH * NT];
__device__ float g_edst[BATCH * NH * NT];

// ---------------- small kernels ----------------
__global__ void k_init() { g_tmax_u = 0u; }

__global__ void k_tmax(const float4* __restrict__ t, int n4) {
    float m = 0.f;
    for (int i = blockIdx.x * blockDim.x + threadIdx.x; i < n4; i += gridDim.x * blockDim.x) {
        float4 v = t[i];
        m = fmaxf(m, fmaxf(fmaxf(v.x, v.y), fmaxf(v.z, v.w)));
    }
#pragma unroll
    for (int s = 16; s; s >>= 1) m = fmaxf(m, __shfl_xor_sync(0xffffffffu, m, s));
    __shared__ float sm[8];
    if ((threadIdx.x & 31) == 0) sm[threadIdx.x >> 5] = m;
    __syncthreads();
    if (threadIdx.x == 0) {
        for (int w = 1; w < 8; w++) m = fmaxf(m, sm[w]);
        atomicMax(&g_tmax_u, __float_as_uint(m));  // values >= 0 -> uint order == float order
    }
}

__global__ void k_twm(const float4* __restrict__ tm, const int4* __restrict__ adj, int n4) {
    float tmax = __uint_as_float(g_tmax_u);
    int stride = gridDim.x * blockDim.x;
    for (int i = blockIdx.x * blockDim.x + threadIdx.x; i < n4; i += stride) {
        float4 t = tm[i];
        int4 a = adj[i];
        float4 o;
        o.x = a.x ? __expf(-0.1f * (tmax - t.x)) : -1.f;
        o.y = a.y ? __expf(-0.1f * (tmax - t.y)) : -1.f;
        o.z = a.z ? __expf(-0.1f * (tmax - t.z)) : -1.f;
        o.w = a.w ? __expf(-0.1f * (tmax - t.w)) : -1.f;
        reinterpret_cast<float4*>(g_twm)[i] = o;
    }
}

// struct_W [512,128] -> Bt [128,512]
__global__ void k_transB(const float* __restrict__ sW, float* __restrict__ out) {
    int idx = blockIdx.x * 256 + threadIdx.x;  // < 128*512
    int k = idx >> 9, n = idx & 511;
    out[idx] = sW[n * TD + k];
}

// gat_W[l] [8,512,64] -> Wcat [512,512] with Wcat[k][h*64+d]
__global__ void k_transW(const float* __restrict__ gWl, float* __restrict__ out) {
    int idx = blockIdx.x * 256 + threadIdx.x;  // < 512*512
    int k = idx >> 9, c = idx & 511;
    int hh = c >> 6, d = c & 63;
    out[idx] = gWl[hh * (HID * HD) + k * HD + d];
}

// ---------------- 64x64 tiled fp32 GEMM with packed f32x2 FMAs ----------------
// C[M,N] = A[M,K]*B[K,N] (+bias). A staged duplicated: As_dup[k][2m]={a,a}.
__global__ void k_gemm(const float* __restrict__ A, const float* __restrict__ B,
                       float* __restrict__ C, const float* __restrict__ bias,
                       int K, int N) {
    __shared__ float As_dup[32][140];   // [k][2m], stride 140 keeps 16B align, 4-way max STS conflict
    __shared__ float Bs[32][68];
    int t = threadIdx.x;
    int tx = t & 15, ty = t >> 4;
    int m0 = blockIdx.x * 64, n0 = blockIdx.y * 64;
    u64 acc[4][2] = {};
    int ar = t >> 3, akc = (t & 7) * 4;
    int bk = t >> 3, bnc = (t & 7) * 8;

    for (int kt = 0; kt < K; kt += 32) {
#pragma unroll
        for (int rr = 0; rr < 64; rr += 32) {
            float4 v = *reinterpret_cast<const float4*>(A + (size_t)(m0 + ar + rr) * K + kt + akc);
            int m2 = 2 * (ar + rr);
            *reinterpret_cast<float2*>(&As_dup[akc + 0][m2]) = make_float2(v.x, v.x);
            *reinterpret_cast<float2*>(&As_dup[akc + 1][m2]) = make_float2(v.y, v.y);
            *reinterpret_cast<float2*>(&As_dup[akc + 2][m2]) = make_float2(v.z, v.z);
            *reinterpret_cast<float2*>(&As_dup[akc + 3][m2]) = make_float2(v.w, v.w);
        }
        {
            const float* bp = B + (size_t)(kt + bk) * N + n0 + bnc;
            float4 v0 = *reinterpret_cast<const float4*>(bp);
            float4 v1 = *reinterpret_cast<const float4*>(bp + 4);
            *reinterpret_cast<float4*>(&Bs[bk][bnc]) = v0;
            *reinterpret_cast<float4*>(&Bs[bk][bnc + 4]) = v1;
        }
        __syncthreads();
#pragma unroll
        for (int k = 0; k < 32; k++) {
            ulonglong2 a01 = *reinterpret_cast<const ulonglong2*>(&As_dup[k][ty * 8]);
            ulonglong2 a23 = *reinterpret_cast<const ulonglong2*>(&As_dup[k][ty * 8 + 4]);
            ulonglong2 bb  = *reinterpret_cast<const ulonglong2*>(&Bs[k][tx * 4]);
            ffma2(acc[0][0], a01.x, bb.x); ffma2(acc[0][1], a01.x, bb.y);
            ffma2(acc[1][0], a01.y, bb.x); ffma2(acc[1][1], a01.y, bb.y);
            ffma2(acc[2][0], a23.x, bb.x); ffma2(acc[2][1], a23.x, bb.y);
            ffma2(acc[3][0], a23.y, bb.x); ffma2(acc[3][1], a23.y, bb.y);
        }
        __syncthreads();
    }
    float bx = 0.f, by = 0.f, bz = 0.f, bw = 0.f;
    if (bias) {
        bx = bias[n0 + tx * 4 + 0]; by = bias[n0 + tx * 4 + 1];
        bz = bias[n0 + tx * 4 + 2]; bw = bias[n0 + tx * 4 + 3];
    }
#pragma unroll
    for (int ii = 0; ii < 4; ii++) {
        float4 o;
        unpack2(acc[ii][0], o.x, o.y);
        unpack2(acc[ii][1], o.z, o.w);
        o.x += bx; o.y += by; o.z += bz; o.w += bw;
        *reinterpret_cast<float4*>(C + (size_t)(m0 + ty * 4 + ii) * N + n0 + tx * 4) = o;
    }
}

// ---------------- e_src / e_dst ----------------
__global__ void k_se(const float* __restrict__ h, const float* __restrict__ ga,
                     float* __restrict__ esrc, float* __restrict__ edst, int total) {
    int idx = blockIdx.x * blockDim.x + threadIdx.x;
    if (idx >= total) return;
    int n = idx & (NT - 1);
    int hh = (idx >> 10) & 7;
    int b = idx >> 13;
    const float4* hr = reinterpret_cast<const float4*>(h + ((size_t)(b * NT + n)) * HID + hh * HD);
    const float4* as = reinterpret_cast<const float4*>(ga + hh * 2 * HD);
    const float4* ad = reinterpret_cast<const float4*>(ga + hh * 2 * HD + HD);
    float s = 0.f, d = 0.f;
#pragma unroll
    for (int i = 0; i < 16; i++) {
        float4 hv = hr[i], a1 = as[i], a2 = ad[i];
        s += hv.x * a1.x + hv.y * a1.y + hv.z * a1.z + hv.w * a1.w;
        d += hv.x * a2.x + hv.y * a2.y + hv.z * a2.z + hv.w * a2.w;
    }
    esrc[idx] = s;
    edst[idx] = d;
}

// ---------------- fused GAT attention (flash-style online softmax + P@H, f32x2) ----------------
// grid = 1024 CTAs: blockIdx.x = h + 8*(b + 8*iblk); 256 threads
// smem: h_s[64][68], tw_s[64][68], pd_s[64][136] (p duplicated: pd[j][2i]={p,p}),
//       edst_s[1024], esrc/m/l/al[64]
#define ATTN_SMEM_FLOATS (2 * 64 * 68 + 64 * 136 + 1024 + 4 * 64)
__global__ void __launch_bounds__(256) k_attn(
    const float* __restrict__ gh, const float* __restrict__ esrc,
    const float* __restrict__ edst, const float* __restrict__ twm,
    float* __restrict__ nodeout, int nb) {
    extern __shared__ float sm[];
    float* h_s = sm;                    // [64][68]
    float* tw_s = h_s + 64 * 68;        // [64][68]
    float* pd_s = tw_s + 64 * 68;       // [64][136], pd[j][2i..2i+1] = {p,p}
    float* edst_s = pd_s + 64 * 136;    // [1024]
    float* esrc_s = edst_s + 1024;      // [64]
    float* m_s = esrc_s + 64;           // [64]
    float* l_s = m_s + 64;              // [64]
    float* al_s = l_s + 64;             // [64]

    int t = threadIdx.x;
    int hh = blockIdx.x & 7;
    int rem = blockIdx.x >> 3;
    int b = rem & 7;
    int iblk = rem >> 3;
    int i0 = iblk * 64;
    int bh = (nb == 1) ? 0 : b;

    const float* ed = edst + (size_t)(bh * NH + hh) * NT;
    for (int u = t; u < NT; u += 256) edst_s[u] = ed[u];
    if (t < 64) {
        esrc_s[t] = esrc[(size_t)(bh * NH + hh) * NT + i0 + t];
        m_s[t] = -1e30f;
        l_s[t] = 0.f;
    }

    int ty = t >> 4, tx = t & 15;
    u64 acc[4][2] = {};

    int pi = t >> 2;   // phase-1 row
    int q = t & 3;

    const float* hbase = gh + (size_t)bh * NT * HID + hh * HD;
    const float* twbase = twm + ((size_t)b * NT + i0) * NT;

    int lr = t >> 2;               // tile-load row (0..63)
    int lc = (t & 3) * 16;         // tile-load col start

    __syncthreads();

    for (int j0 = 0; j0 < NT; j0 += 64) {
        // cooperative loads: h tile [64j][64d], twm tile [64i][64j]
        {
            const float4* src = reinterpret_cast<const float4*>(hbase + (size_t)(j0 + lr) * HID + lc);
            float4* dst = reinterpret_cast<float4*>(h_s + lr * 68 + lc);
            dst[0] = src[0]; dst[1] = src[1]; dst[2] = src[2]; dst[3] = src[3];
            const float4* ts = reinterpret_cast<const float4*>(twbase + (size_t)lr * NT + j0 + lc);
            float4* td = reinterpret_cast<float4*>(tw_s + lr * 68 + lc);
            td[0] = ts[0]; td[1] = ts[1]; td[2] = ts[2]; td[3] = ts[3];
        }
        __syncthreads();

        // phase 1: e + online softmax for row pi (4 threads/row, 16 j each)
        float es = esrc_s[pi];
        float e_reg[16];
        float lmax = -1e30f;
#pragma unroll
        for (int jj = 0; jj < 16; jj++) {
            int j = q + 4 * jj;
            float tw = tw_s[pi * 68 + j];
            float raw = es + edst_s[j0 + j];
            float leak = raw > 0.f ? raw : 0.2f * raw;
            float e = (tw < 0.f) ? -1e30f : leak * tw;
            e_reg[jj] = e;
            lmax = fmaxf(lmax, e);
        }
        lmax = fmaxf(lmax, __shfl_xor_sync(0xffffffffu, lmax, 1));
        lmax = fmaxf(lmax, __shfl_xor_sync(0xffffffffu, lmax, 2));
        float mold = m_s[pi];
        float mnew = fmaxf(mold, lmax);
        float lsum = 0.f;
#pragma unroll
        for (int jj = 0; jj < 16; jj++) {
            int j = q + 4 * jj;
            float p = __expf(e_reg[jj] - mnew);
            *reinterpret_cast<float2*>(pd_s + j * 136 + 2 * pi) = make_float2(p, p);
            lsum += p;
        }
        lsum += __shfl_xor_sync(0xffffffffu, lsum, 1);
        lsum += __shfl_xor_sync(0xffffffffu, lsum, 2);
        if (q == 0) {
            float alpha = __expf(mold - mnew);
            al_s[pi] = alpha;
            m_s[pi] = mnew;
            l_s[pi] = l_s[pi] * alpha + lsum;
        }
        __syncthreads();

        // phase 2: acc = acc*alpha + P^T tile GEMM (4x4 per thread, packed f32x2)
        {
            u64 ap0 = pack2(al_s[ty * 4 + 0], al_s[ty * 4 + 0]);
            u64 ap1 = pack2(al_s[ty * 4 + 1], al_s[ty * 4 + 1]);
            u64 ap2 = pack2(al_s[ty * 4 + 2], al_s[ty * 4 + 2]);
            u64 ap3 = pack2(al_s[ty * 4 + 3], al_s[ty * 4 + 3]);
            fmul2(acc[0][0], acc[0][0], ap0); fmul2(acc[0][1], acc[0][1], ap0);
            fmul2(acc[1][0], acc[1][0], ap1); fmul2(acc[1][1], acc[1][1], ap1);
            fmul2(acc[2][0], acc[2][0], ap2); fmul2(acc[2][1], acc[2][1], ap2);
            fmul2(acc[3][0], acc[3][0], ap3); fmul2(acc[3][1], acc[3][1], ap3);
        }
#pragma unroll 4
        for (int j = 0; j < 64; j++) {
            ulonglong2 p01 = *reinterpret_cast<const ulonglong2*>(pd_s + j * 136 + ty * 8);
            ulonglong2 p23 = *reinterpret_cast<const ulonglong2*>(pd_s + j * 136 + ty * 8 + 4);
            ulonglong2 hv  = *reinterpret_cast<const ulonglong2*>(h_s + j * 68 + tx * 4);
            ffma2(acc[0][0], p01.x, hv.x); ffma2(acc[0][1], p01.x, hv.y);
            ffma2(acc[1][0], p01.y, hv.x); ffma2(acc[1][1], p01.y, hv.y);
            ffma2(acc[2][0], p23.x, hv.x); ffma2(acc[2][1], p23.x, hv.y);
            ffma2(acc[3][0], p23.y, hv.x); ffma2(acc[3][1], p23.y, hv.y);
        }
        __syncthreads();
    }

    // finalize: out = elu(acc / l)
#pragma unroll
    for (int ii = 0; ii < 4; ii++) {
        int i = ty * 4 + ii;
        float inv = 1.f / l_s[i];
        float v0, v1, v2, v3;
        unpack2(acc[ii][0], v0, v1);
        unpack2(acc[ii][1], v2, v3);
        v0 *= inv; v1 *= inv; v2 *= inv; v3 *= inv;
        float4 o;
        o.x = v0 > 0.f ? v0 : (__expf(v0) - 1.f);
        o.y = v1 > 0.f ? v1 : (__expf(v1) - 1.f);
        o.z = v2 > 0.f ? v2 : (__expf(v2) - 1.f);
        o.w = v3 > 0.f ? v3 : (__expf(v3) - 1.f);
        *reinterpret_cast<float4*>(nodeout + ((size_t)b * NT + i0 + i) * HID + hh * HD + tx * 4) = o;
    }
}

// ---------------- final MLP ----------------
__global__ void k_final(const float* __restrict__ node, const int* __restrict__ topic_ids,
                        const float* __restrict__ attractiveness,
                        const float* __restrict__ aW, const float* __restrict__ ab,
                        const float* __restrict__ f1W, const float* __restrict__ f1b,
                        const float* __restrict__ f2W, const float* __restrict__ f2b,
                        float* __restrict__ out) {
    int b = blockIdx.x;
    int t = threadIdx.x;  // 512
    __shared__ float comb[HID];
    __shared__ float red[16];
    int tid = topic_ids[b];
    float av = attractiveness[b];
    comb[t] = node[((size_t)b * NT + tid) * HID + t] + av * aW[t] + ab[t];
    __syncthreads();
    float acc = f1b[t];
    const float4* w = reinterpret_cast<const float4*>(f1W + (size_t)t * HID);
    const float4* c4 = reinterpret_cast<const float4*>(comb);
#pragma unroll 8
    for (int o = 0; o < HID / 4; o++) {
        float4 wv = w[o], cv = c4[o];
        acc += wv.x * cv.x + wv.y * cv.y + wv.z * cv.z + wv.w * cv.w;
    }
    acc = fmaxf(acc, 0.f);
    float p = acc * f2W[t];
#pragma unroll
    for (int s = 16; s; s >>= 1) p += __shfl_xor_sync(0xffffffffu, p, s);
    if ((t & 31) == 0) red[t >> 5] = p;
    __syncthreads();
    if (t < 16) {
        float v = red[t];
#pragma unroll
        for (int s = 8; s; s >>= 1) v += __shfl_xor_sync(0xffffu, v, s);
        if (t == 0) out[b] = v + f2b[0];
    }
}

// ---------------- launch ----------------
extern "C" void kernel_launch(void* const* d_in, const int* in_sizes, int n_in,
                              void* d_out, int out_size) {
    const int*   topic_ids = (const int*)d_in[0];
    const int*   adj       = (const int*)d_in[1];
    const float* timem     = (const float*)d_in[2];
    const float* attract   = (const float*)d_in[3];
    const float* emb       = (const float*)d_in[4];
    const float* sW        = (const float*)d_in[5];
    const float* sb        = (const float*)d_in[6];
    const float* aW        = (const float*)d_in[7];
    const float* ab        = (const float*)d_in[8];
    const float* gW        = (const float*)d_in[9];
    const float* ga        = (const float*)d_in[10];
    const float* f1W       = (const float*)d_in[11];
    const float* f1b       = (const float*)d_in[12];
    const float* f2W       = (const float*)d_in[13];
    const float* f2b       = (const float*)d_in[14];
    float* out = (float*)d_out;

    void *pv;
    cudaGetSymbolAddress(&pv, g_twm);    float* twm  = (float*)pv;
    cudaGetSymbolAddress(&pv, g_struct); float* gstr = (float*)pv;
    cudaGetSymbolAddress(&pv, g_bt);     float* bt   = (float*)pv;
    cudaGetSymbolAddress(&pv, g_h);      float* h    = (float*)pv;
    cudaGetSymbolAddress(&pv, g_node);   float* node = (float*)pv;
    cudaGetSymbolAddress(&pv, g_esrc);   float* esrc = (float*)pv;
    cudaGetSymbolAddress(&pv, g_edst);   float* edst = (float*)pv;

    const int attn_smem = ATTN_SMEM_FLOATS * (int)sizeof(float);  // 74752 B
    cudaFuncSetAttribute(k_attn, cudaFuncAttributeMaxDynamicSharedMemorySize, attn_smem);

    int n4 = (BATCH * NT * NT) / 4;
    k_init<<<1, 1>>>();
    k_tmax<<<2048, 256>>>(reinterpret_cast<const float4*>(timem), n4);
    k_twm<<<4096, 256>>>(reinterpret_cast<const float4*>(timem),
                         reinterpret_cast<const int4*>(adj), n4);

    // struct = emb @ struct_W^T + b
    k_transB<<<(TD * HID) / 256, 256>>>(sW, bt);
    k_gemm<<<dim3(NT / 64, HID / 64), 256>>>(emb, bt, gstr, sb, TD, HID);

    for (int l = 0; l < 2; l++) {
        int nb = (l == 0) ? 1 : BATCH;
        k_transW<<<(HID * HID) / 256, 256>>>(gW + (size_t)l * NH * HID * HD, bt);
        const float* node_in = (l == 0) ? gstr : node;
        k_gemm<<<dim3(nb * NT / 64, HID / 64), 256>>>(node_in, bt, h, nullptr, HID, HID);
        k_se<<<(nb * NH * NT) / 256, 256>>>(h, ga + (size_t)l * NH * 2 * HD, esrc, edst, nb * NH * NT);
        k_attn<<<BATCH * NH * (NT / 64), 256, attn_smem>>>(h, esrc, edst, twm, node, nb);
    }

    k_final<<<BATCH, 512>>>(node, topic_ids, attract, aW, ab, f1W, f1b, f2W, f2b, out);
}

// round 5
// speedup vs baseline: 1.2707x; 1.2707x over previous
#include <cuda_runtime.h>
#include <math.h>
#include <stddef.h>
#include <stdint.h>

#define BATCH 8
#define NT 1024
#define TD 128
#define HID 512
#define NH 8
#define HD 64

// ---------------- helpers ----------------
__device__ __forceinline__ float tf32r(float x){
    uint32_t u; asm("cvt.rna.tf32.f32 %0, %1;" : "=r"(u) : "f"(x));
    return __uint_as_float(u);
}
__device__ __forceinline__ void mma_tf32(float* c,
    uint32_t a0, uint32_t a1, uint32_t a2, uint32_t a3,
    uint32_t b0, uint32_t b1){
    asm("mma.sync.aligned.m16n8k8.row.col.f32.tf32.tf32.f32 "
        "{%0,%1,%2,%3}, {%4,%5,%6,%7}, {%8,%9}, {%0,%1,%2,%3};"
        : "+f"(c[0]), "+f"(c[1]), "+f"(c[2]), "+f"(c[3])
        : "r"(a0), "r"(a1), "r"(a2), "r"(a3), "r"(b0), "r"(b1));
}

// ---------------- device scratch (static; no allocation) ----------------
__device__ unsigned g_tmax_u;
__device__ float g_twm[BATCH * NT * NT];     // adj ? exp(-0.1*(tmax-t)) : -1
__device__ float g_struct[NT * HID];
__device__ float g_bt[HID * HID];            // transposed weight staging
__device__ float g_h[BATCH * NT * HID];      // h per (b,n,[h*64+d])
__device__ float g_node[BATCH * NT * HID];   // GAT layer output
__device__ float g_esrc[BATCH * NH * NT];
__device__ float g_edst[BATCH * NH * NT];

// ---------------- small kernels ----------------
__global__ void k_init() { g_tmax_u = 0u; }

__global__ void k_tmax(const float4* __restrict__ t, int n4) {
    float m = 0.f;
    for (int i = blockIdx.x * blockDim.x + threadIdx.x; i < n4; i += gridDim.x * blockDim.x) {
        float4 v = t[i];
        m = fmaxf(m, fmaxf(fmaxf(v.x, v.y), fmaxf(v.z, v.w)));
    }
#pragma unroll
    for (int s = 16; s; s >>= 1) m = fmaxf(m, __shfl_xor_sync(0xffffffffu, m, s));
    __shared__ float sm[8];
    if ((threadIdx.x & 31) == 0) sm[threadIdx.x >> 5] = m;
    __syncthreads();
    if (threadIdx.x == 0) {
        for (int w = 1; w < 8; w++) m = fmaxf(m, sm[w]);
        atomicMax(&g_tmax_u, __float_as_uint(m));  // values >= 0 -> uint order == float order
    }
}

__global__ void k_twm(const float4* __restrict__ tm, const int4* __restrict__ adj, int n4) {
    float tmax = __uint_as_float(g_tmax_u);
    int stride = gridDim.x * blockDim.x;
    for (int i = blockIdx.x * blockDim.x + threadIdx.x; i < n4; i += stride) {
        float4 t = tm[i];
        int4 a = adj[i];
        float4 o;
        o.x = a.x ? __expf(-0.1f * (tmax - t.x)) : -1.f;
        o.y = a.y ? __expf(-0.1f * (tmax - t.y)) : -1.f;
        o.z = a.z ? __expf(-0.1f * (tmax - t.z)) : -1.f;
        o.w = a.w ? __expf(-0.1f * (tmax - t.w)) : -1.f;
        reinterpret_cast<float4*>(g_twm)[i] = o;
    }
}

// struct_W [512,128] -> Bt [128,512]
__global__ void k_transB(const float* __restrict__ sW, float* __restrict__ out) {
    int idx = blockIdx.x * 256 + threadIdx.x;  // < 128*512
    int k = idx >> 9, n = idx & 511;
    out[idx] = sW[n * TD + k];
}

// gat_W[l] [8,512,64] -> Wcat [512,512] with Wcat[k][h*64+d]
__global__ void k_transW(const float* __restrict__ gWl, float* __restrict__ out) {
    int idx = blockIdx.x * 256 + threadIdx.x;  // < 512*512
    int k = idx >> 9, c = idx & 511;
    int hh = c >> 6, d = c & 63;
    out[idx] = gWl[hh * (HID * HD) + k * HD + d];
}

// ---------------- generic 64x64 tiled fp32 GEMM ----------------
__global__ void k_gemm(const float* __restrict__ A, const float* __restrict__ B,
                       float* __restrict__ C, const float* __restrict__ bias,
                       int K, int N) {
    __shared__ float As[32][68];
    __shared__ float Bs[32][68];
    int t = threadIdx.x;
    int tx = t & 15, ty = t >> 4;
    int m0 = blockIdx.x * 64, n0 = blockIdx.y * 64;
    float acc[4][4] = {};
    int ar = t >> 3, akc = (t & 7) * 4;
    int bk = t >> 3, bnc = (t & 7) * 8;

    for (int kt = 0; kt < K; kt += 32) {
#pragma unroll
        for (int rr = 0; rr < 64; rr += 32) {
            float4 v = *reinterpret_cast<const float4*>(A + (size_t)(m0 + ar + rr) * K + kt + akc);
            As[akc + 0][ar + rr] = v.x;
            As[akc + 1][ar + rr] = v.y;
            As[akc + 2][ar + rr] = v.z;
            As[akc + 3][ar + rr] = v.w;
        }
        {
            const float* bp = B + (size_t)(kt + bk) * N + n0 + bnc;
            float4 v0 = *reinterpret_cast<const float4*>(bp);
            float4 v1 = *reinterpret_cast<const float4*>(bp + 4);
            *reinterpret_cast<float4*>(&Bs[bk][bnc]) = v0;
            *reinterpret_cast<float4*>(&Bs[bk][bnc + 4]) = v1;
        }
        __syncthreads();
#pragma unroll
        for (int k = 0; k < 32; k++) {
            float4 a4 = *reinterpret_cast<const float4*>(&As[k][ty * 4]);
            float4 b4 = *reinterpret_cast<const float4*>(&Bs[k][tx * 4]);
            acc[0][0] += a4.x * b4.x; acc[0][1] += a4.x * b4.y; acc[0][2] += a4.x * b4.z; acc[0][3] += a4.x * b4.w;
            acc[1][0] += a4.y * b4.x; acc[1][1] += a4.y * b4.y; acc[1][2] += a4.y * b4.z; acc[1][3] += a4.y * b4.w;
            acc[2][0] += a4.z * b4.x; acc[2][1] += a4.z * b4.y; acc[2][2] += a4.z * b4.z; acc[2][3] += a4.z * b4.w;
            acc[3][0] += a4.w * b4.x; acc[3][1] += a4.w * b4.y; acc[3][2] += a4.w * b4.z; acc[3][3] += a4.w * b4.w;
        }
        __syncthreads();
    }
    float bx = 0.f, by = 0.f, bz = 0.f, bw = 0.f;
    if (bias) {
        bx = bias[n0 + tx * 4 + 0]; by = bias[n0 + tx * 4 + 1];
        bz = bias[n0 + tx * 4 + 2]; bw = bias[n0 + tx * 4 + 3];
    }
#pragma unroll
    for (int ii = 0; ii < 4; ii++) {
        float4 o;
        o.x = acc[ii][0] + bx; o.y = acc[ii][1] + by; o.z = acc[ii][2] + bz; o.w = acc[ii][3] + bw;
        *reinterpret_cast<float4*>(C + (size_t)(m0 + ty * 4 + ii) * N + n0 + tx * 4) = o;
    }
}

// ---------------- e_src / e_dst ----------------
__global__ void k_se(const float* __restrict__ h, const float* __restrict__ ga,
                     float* __restrict__ esrc, float* __restrict__ edst, int total) {
    int idx = blockIdx.x * blockDim.x + threadIdx.x;
    if (idx >= total) return;
    int n = idx & (NT - 1);
    int hh = (idx >> 10) & 7;
    int b = idx >> 13;
    const float4* hr = reinterpret_cast<const float4*>(h + ((size_t)(b * NT + n)) * HID + hh * HD);
    const float4* as = reinterpret_cast<const float4*>(ga + hh * 2 * HD);
    const float4* ad = reinterpret_cast<const float4*>(ga + hh * 2 * HD + HD);
    float s = 0.f, d = 0.f;
#pragma unroll
    for (int i = 0; i < 16; i++) {
        float4 hv = hr[i], a1 = as[i], a2 = ad[i];
        s += hv.x * a1.x + hv.y * a1.y + hv.z * a1.z + hv.w * a1.w;
        d += hv.x * a2.x + hv.y * a2.y + hv.z * a2.z + hv.w * a2.w;
    }
    esrc[idx] = s;
    edst[idx] = d;
}

// ---------------- mma.sync tf32 fused GAT attention ----------------
// CTA = (head, batch, 128-row i-block), 256 threads, 8 warps x 16 rows.
// Single-pass softmax with a-priori bound m_i = max(es_i + max_j(ed_j), 0);
// P rounded to tf32 (exact in both l and the MMA); H split hi/lo (3xTF32).
// smem floats: tw[128*36] + hhi[32*72] + hlo[32*72] + edst[1024] + red[8]
#define ATTN_SMEM_FLOATS (128 * 36 + 2 * 32 * 72 + 1024 + 8)
__global__ void __launch_bounds__(256) k_attn(
    const float* __restrict__ gh, const float* __restrict__ esrc,
    const float* __restrict__ edst, const float* __restrict__ twm,
    float* __restrict__ nodeout, int nb) {
    extern __shared__ float sm[];
    float* tw_s  = sm;                     // [128][36]
    float* hhi_s = tw_s + 128 * 36;        // [32][72]
    float* hlo_s = hhi_s + 32 * 72;        // [32][72]
    float* edst_s = hlo_s + 32 * 72;       // [1024]
    float* red_s  = edst_s + 1024;         // [8]

    int t = threadIdx.x;
    int wid = t >> 5, lid = t & 31;
    int hh = blockIdx.x & 7;
    int rem = blockIdx.x >> 3;
    int b = rem & 7;
    int iblk = rem >> 3;
    int i0 = iblk * 128;
    int bh = (nb == 1) ? 0 : b;

    // edst row -> smem, and its max
    const float* ed = edst + (size_t)(bh * NH + hh) * NT;
    float vmax = -1e30f;
    for (int u = t; u < NT; u += 256) { float v = ed[u]; edst_s[u] = v; vmax = fmaxf(vmax, v); }
#pragma unroll
    for (int s = 16; s; s >>= 1) vmax = fmaxf(vmax, __shfl_xor_sync(0xffffffffu, vmax, s));
    if (lid == 0) red_s[wid] = vmax;
    __syncthreads();
    float edmax = red_s[0];
#pragma unroll
    for (int w = 1; w < 8; w++) edmax = fmaxf(edmax, red_s[w]);

    int g = lid >> 2, q = lid & 3;
    int r0 = wid * 16 + g, r1 = r0 + 8;
    const float* esp = esrc + (size_t)(bh * NH + hh) * NT + i0;
    float es0 = esp[r0], es1 = esp[r1];
    float m0 = fmaxf(es0 + edmax, 0.f), m1 = fmaxf(es1 + edmax, 0.f);

    float acc[8][4] = {};
    float l0 = 0.f, l1 = 0.f;

    const float* twbase = twm + ((size_t)b * NT + i0) * NT;
    const float* hbase  = gh + (size_t)bh * NT * HID + hh * HD;

    int srow = t >> 1, scol = (t & 1) * 16;   // tw staging: 128 rows x 32 cols
    int hrow = t >> 3, hcol = (t & 7) * 8;    // h staging: 32 rows x 64 cols

    for (int T = 0; T < NT / 32; T++) {
        int j0 = T * 32;
        // ---- stage tw tile [128 i][32 j] ----
        {
            const float* tp = twbase + (size_t)srow * NT + j0 + scol;
            float4 v0 = *reinterpret_cast<const float4*>(tp);
            float4 v1 = *reinterpret_cast<const float4*>(tp + 4);
            float4 v2 = *reinterpret_cast<const float4*>(tp + 8);
            float4 v3 = *reinterpret_cast<const float4*>(tp + 12);
            float* td = tw_s + srow * 36 + scol;
            *reinterpret_cast<float4*>(td)      = v0;
            *reinterpret_cast<float4*>(td + 4)  = v1;
            *reinterpret_cast<float4*>(td + 8)  = v2;
            *reinterpret_cast<float4*>(td + 12) = v3;
        }
        // ---- stage h tile [32 j][64 d], tf32 hi/lo split ----
        {
            const float* hp = hbase + (size_t)(j0 + hrow) * HID + hcol;
            float4 a = *reinterpret_cast<const float4*>(hp);
            float4 c = *reinterpret_cast<const float4*>(hp + 4);
            float4 ahi, alo, chi, clo;
            ahi.x = tf32r(a.x); alo.x = tf32r(a.x - ahi.x);
            ahi.y = tf32r(a.y); alo.y = tf32r(a.y - ahi.y);
            ahi.z = tf32r(a.z); alo.z = tf32r(a.z - ahi.z);
            ahi.w = tf32r(a.w); alo.w = tf32r(a.w - ahi.w);
            chi.x = tf32r(c.x); clo.x = tf32r(c.x - chi.x);
            chi.y = tf32r(c.y); clo.y = tf32r(c.y - chi.y);
            chi.z = tf32r(c.z); clo.z = tf32r(c.z - chi.z);
            chi.w = tf32r(c.w); clo.w = tf32r(c.w - chi.w);
            float* dh = hhi_s + hrow * 72 + hcol;
            float* dl = hlo_s + hrow * 72 + hcol;
            *reinterpret_cast<float4*>(dh)     = ahi;
            *reinterpret_cast<float4*>(dh + 4) = chi;
            *reinterpret_cast<float4*>(dl)     = alo;
            *reinterpret_cast<float4*>(dl + 4) = clo;
        }
        __syncthreads();

#pragma unroll
        for (int kc = 0; kc < 4; kc++) {
            int c0 = kc * 8 + q, c1 = c0 + 4;
            float ed0 = edst_s[j0 + c0], ed1 = edst_s[j0 + c1];
            float tw00 = tw_s[r0 * 36 + c0], tw01 = tw_s[r0 * 36 + c1];
            float tw10 = tw_s[r1 * 36 + c0], tw11 = tw_s[r1 * 36 + c1];
            float x, lk;
            x = es0 + ed0; lk = fmaxf(x, 0.2f * x);
            float p00 = (tw00 < 0.f) ? 0.f : tf32r(__expf(lk * tw00 - m0));
            x = es0 + ed1; lk = fmaxf(x, 0.2f * x);
            float p01 = (tw01 < 0.f) ? 0.f : tf32r(__expf(lk * tw01 - m0));
            x = es1 + ed0; lk = fmaxf(x, 0.2f * x);
            float p10 = (tw10 < 0.f) ? 0.f : tf32r(__expf(lk * tw10 - m1));
            x = es1 + ed1; lk = fmaxf(x, 0.2f * x);
            float p11 = (tw11 < 0.f) ? 0.f : tf32r(__expf(lk * tw11 - m1));
            l0 += p00 + p01;
            l1 += p10 + p11;
            uint32_t A0 = __float_as_uint(p00), A1 = __float_as_uint(p10);
            uint32_t A2 = __float_as_uint(p01), A3 = __float_as_uint(p11);
            const float* bh0p = hhi_s + c0 * 72 + g;
            const float* bh1p = hhi_s + c1 * 72 + g;
            const float* bl0p = hlo_s + c0 * 72 + g;
            const float* bl1p = hlo_s + c1 * 72 + g;
#pragma unroll
            for (int nbk = 0; nbk < 8; nbk++) {
                uint32_t b0 = __float_as_uint(bh0p[nbk * 8]);
                uint32_t b1 = __float_as_uint(bh1p[nbk * 8]);
                mma_tf32(acc[nbk], A0, A1, A2, A3, b0, b1);
                uint32_t b2 = __float_as_uint(bl0p[nbk * 8]);
                uint32_t b3 = __float_as_uint(bl1p[nbk * 8]);
                mma_tf32(acc[nbk], A0, A1, A2, A3, b2, b3);
            }
        }
        __syncthreads();
    }

    // reduce l within quads (lanes sharing the same rows)
    l0 += __shfl_xor_sync(0xffffffffu, l0, 1);
    l0 += __shfl_xor_sync(0xffffffffu, l0, 2);
    l1 += __shfl_xor_sync(0xffffffffu, l1, 1);
    l1 += __shfl_xor_sync(0xffffffffu, l1, 2);
    float inv0 = 1.f / l0, inv1 = 1.f / l1;

    // epilogue: elu(acc/l) straight from fragments
    float* o0 = nodeout + ((size_t)b * NT + i0 + r0) * HID + hh * HD;
    float* o1 = nodeout + ((size_t)b * NT + i0 + r1) * HID + hh * HD;
#pragma unroll
    for (int nbk = 0; nbk < 8; nbk++) {
        int col = nbk * 8 + q * 2;
        float v0 = acc[nbk][0] * inv0, v1 = acc[nbk][1] * inv0;
        float v2 = acc[nbk][2] * inv1, v3 = acc[nbk][3] * inv1;
        float2 w0, w1;
        w0.x = v0 > 0.f ? v0 : (__expf(v0) - 1.f);
        w0.y = v1 > 0.f ? v1 : (__expf(v1) - 1.f);
        w1.x = v2 > 0.f ? v2 : (__expf(v2) - 1.f);
        w1.y = v3 > 0.f ? v3 : (__expf(v3) - 1.f);
        *reinterpret_cast<float2*>(o0 + col) = w0;
        *reinterpret_cast<float2*>(o1 + col) = w1;
    }
}

// ---------------- final MLP ----------------
__global__ void k_final(const float* __restrict__ node, const int* __restrict__ topic_ids,
                        const float* __restrict__ attractiveness,
                        const float* __restrict__ aW, const float* __restrict__ ab,
                        const float* __restrict__ f1W, const float* __restrict__ f1b,
                        const float* __restrict__ f2W, const float* __restrict__ f2b,
                        float* __restrict__ out) {
    int b = blockIdx.x;
    int t = threadIdx.x;  // 512
    __shared__ float comb[HID];
    __shared__ float red[16];
    int tid = topic_ids[b];
    float av = attractiveness[b];
    comb[t] = node[((size_t)b * NT + tid) * HID + t] + av * aW[t] + ab[t];
    __syncthreads();
    float acc = f1b[t];
    const float4* w = reinterpret_cast<const float4*>(f1W + (size_t)t * HID);
    const float4* c4 = reinterpret_cast<const float4*>(comb);
#pragma unroll 8
    for (int o = 0; o < HID / 4; o++) {
        float4 wv = w[o], cv = c4[o];
        acc += wv.x * cv.x + wv.y * cv.y + wv.z * cv.z + wv.w * cv.w;
    }
    acc = fmaxf(acc, 0.f);
    float p = acc * f2W[t];
#pragma unroll
    for (int s = 16; s; s >>= 1) p += __shfl_xor_sync(0xffffffffu, p, s);
    if ((t & 31) == 0) red[t >> 5] = p;
    __syncthreads();
    if (t < 16) {
        float v = red[t];
#pragma unroll
        for (int s = 8; s; s >>= 1) v += __shfl_xor_sync(0xffffu, v, s);
        if (t == 0) out[b] = v + f2b[0];
    }
}

// ---------------- launch ----------------
extern "C" void kernel_launch(void* const* d_in, const int* in_sizes, int n_in,
                              void* d_out, int out_size) {
    const int*   topic_ids = (const int*)d_in[0];
    const int*   adj       = (const int*)d_in[1];
    const float* timem     = (const float*)d_in[2];
    const float* attract   = (const float*)d_in[3];
    const float* emb       = (const float*)d_in[4];
    const float* sW        = (const float*)d_in[5];
    const float* sb        = (const float*)d_in[6];
    const float* aW        = (const float*)d_in[7];
    const float* ab        = (const float*)d_in[8];
    const float* gW        = (const float*)d_in[9];
    const float* ga        = (const float*)d_in[10];
    const float* f1W       = (const float*)d_in[11];
    const float* f1b       = (const float*)d_in[12];
    const float* f2W       = (const float*)d_in[13];
    const float* f2b       = (const float*)d_in[14];
    float* out = (float*)d_out;

    void *pv;
    cudaGetSymbolAddress(&pv, g_twm);    float* twm  = (float*)pv;
    cudaGetSymbolAddress(&pv, g_struct); float* gstr = (float*)pv;
    cudaGetSymbolAddress(&pv, g_bt);     float* bt   = (float*)pv;
    cudaGetSymbolAddress(&pv, g_h);      float* h    = (float*)pv;
    cudaGetSymbolAddress(&pv, g_node);   float* node = (float*)pv;
    cudaGetSymbolAddress(&pv, g_esrc);   float* esrc = (float*)pv;
    cudaGetSymbolAddress(&pv, g_edst);   float* edst = (float*)pv;

    const int attn_smem = ATTN_SMEM_FLOATS * (int)sizeof(float);  // ~41KB
    cudaFuncSetAttribute(k_attn, cudaFuncAttributeMaxDynamicSharedMemorySize, attn_smem);

    int n4 = (BATCH * NT * NT) / 4;
    k_init<<<1, 1>>>();
    k_tmax<<<2048, 256>>>(reinterpret_cast<const float4*>(timem), n4);
    k_twm<<<4096, 256>>>(reinterpret_cast<const float4*>(timem),
                         reinterpret_cast<const int4*>(adj), n4);

    // struct = emb @ struct_W^T + b
    k_transB<<<(TD * HID) / 256, 256>>>(sW, bt);
    k_gemm<<<dim3(NT / 64, HID / 64), 256>>>(emb, bt, gstr, sb, TD, HID);

    for (int l = 0; l < 2; l++) {
        int nb = (l == 0) ? 1 : BATCH;
        k_transW<<<(HID * HID) / 256, 256>>>(gW + (size_t)l * NH * HID * HD, bt);
        const float* node_in = (l == 0) ? gstr : node;
        k_gemm<<<dim3(nb * NT / 64, HID / 64), 256>>>(node_in, bt, h, nullptr, HID, HID);
        k_se<<<(nb * NH * NT) / 256, 256>>>(h, ga + (size_t)l * NH * 2 * HD, esrc, edst, nb * NH * NT);
        k_attn<<<BATCH * NH * (NT / 128), 256, attn_smem>>>(h, esrc, edst, twm, node, nb);
    }

    k_final<<<BATCH, 512>>>(node, topic_ids, attract, aW, ab, f1W, f1b, f2W, f2b, out);
}